// round 1
// baseline (speedup 1.0000x reference)
#include <cuda_runtime.h>
#include <math.h>

#define DIMC 512
#define HC   1024
#define BC   64
#define VC   64
#define JT   8   // j-tile per block

// scratch: [0:64*1024) cause_h, [64*1024:128*1024) effect_h, [128*1024:192*1024) ctx_h
__device__ float g_pre[3 * BC * HC];

// ---------------------------------------------------------------------------
// Kernel 1: pre-activations. grid = 3*8 blocks (m, 128-col tile), 256 threads.
//   m=0: cause_h = embed @ W1[0:512]
//   m=1: effect_h = embed @ W1[512:1024]
//   m=2: ctx_h = (state+action) @ W1[1024:1536]
// ---------------------------------------------------------------------------
__global__ void gemm_pre_kernel(const float* __restrict__ state,
                                const float* __restrict__ action,
                                const float* __restrict__ embed,
                                const float* __restrict__ W1) {
    const int m  = blockIdx.x >> 3;   // 0..2
    const int hb = blockIdx.x & 7;    // 0..7 -> cols hb*128 .. +128
    const int tid = threadIdx.x;      // 256 threads

    __shared__ float As[64][17];      // [row][k] padded
    __shared__ float Ws[16][128];     // [k][col]

    const int rgrp = tid >> 5;        // 0..7 -> rows rgrp*8 .. +8
    const int cgrp = tid & 31;        // cols cgrp*4 .. +4

    float acc[8][4];
#pragma unroll
    for (int i = 0; i < 8; ++i)
#pragma unroll
        for (int j = 0; j < 4; ++j) acc[i][j] = 0.0f;

    const float* Wbase = W1 + (size_t)(m * DIMC) * HC + hb * 128;

    for (int k0 = 0; k0 < DIMC; k0 += 16) {
        // load A chunk: 64 rows x 16 k
        for (int t = tid; t < 64 * 16; t += 256) {
            int r = t >> 4, k = t & 15;
            float a;
            if (m == 2) a = state[r * DIMC + k0 + k] + action[r * DIMC + k0 + k];
            else        a = embed[r * DIMC + k0 + k];
            As[r][k] = a;
        }
        // load W chunk: 16 x 128
        for (int t = tid; t < 16 * 128; t += 256) {
            int k = t >> 7, c = t & 127;
            Ws[k][c] = Wbase[(size_t)(k0 + k) * HC + c];
        }
        __syncthreads();
#pragma unroll
        for (int k = 0; k < 16; ++k) {
            float4 w4 = *reinterpret_cast<const float4*>(&Ws[k][cgrp * 4]);
#pragma unroll
            for (int i = 0; i < 8; ++i) {
                float a = As[rgrp * 8 + i][k];
                acc[i][0] = fmaf(a, w4.x, acc[i][0]);
                acc[i][1] = fmaf(a, w4.y, acc[i][1]);
                acc[i][2] = fmaf(a, w4.z, acc[i][2]);
                acc[i][3] = fmaf(a, w4.w, acc[i][3]);
            }
        }
        __syncthreads();
    }

    float* out = g_pre + (size_t)(m * BC) * HC;
#pragma unroll
    for (int i = 0; i < 8; ++i) {
        int r = rgrp * 8 + i;
        float4 v = make_float4(acc[i][0], acc[i][1], acc[i][2], acc[i][3]);
        *reinterpret_cast<float4*>(&out[(size_t)r * HC + hb * 128 + cgrp * 4]) = v;
    }
}

// ---------------------------------------------------------------------------
// Kernel 2: scores[i][j] = mean_b sigmoid(b2 + sum_h w2[h]*gelu(ctx[b,h]+ce[i,j,h]))
// grid = 64 * (64/JT) = 512 blocks; block = (i, j-tile). 256 threads = 8 warps.
// Each warp handles 8 b's; each ctx value loaded once, reused across JT j's.
// ---------------------------------------------------------------------------
__global__ void score_kernel(const float* __restrict__ b1,
                             const float* __restrict__ W2,
                             const float* __restrict__ b2,
                             float* __restrict__ out) {
    const int i  = blockIdx.x >> 3;   // cause index
    const int jt = blockIdx.x & 7;    // effect tile

    __shared__ float ce_s[JT][HC];    // cause+effect+b1
    __shared__ float w2s[HC];
    __shared__ float red[8][JT];

    const int tid  = threadIdx.x;
    const int warp = tid >> 5;
    const int lane = tid & 31;

    const float* cause  = g_pre;
    const float* effect = g_pre + BC * HC;
    const float* ctx    = g_pre + 2 * BC * HC;

    // stage ce and w2
    for (int t = tid; t < JT * HC; t += 256) {
        int j = t >> 10, h = t & (HC - 1);
        ce_s[j][h] = cause[i * HC + h] + effect[(jt * JT + j) * HC + h] + b1[h];
    }
    for (int t = tid; t < HC; t += 256) w2s[t] = W2[t];
    __syncthreads();

    const float bias2 = b2[0];
    float partial[JT];
#pragma unroll
    for (int j = 0; j < JT; ++j) partial[j] = 0.0f;

    for (int bi = 0; bi < 8; ++bi) {
        const int b = bi * 8 + warp;
        const float* ctxb = ctx + (size_t)b * HC;

        float acc[JT];
#pragma unroll
        for (int j = 0; j < JT; ++j) acc[j] = 0.0f;

        for (int h = lane; h < HC; h += 32) {
            const float x = ctxb[h];
            const float w = w2s[h];
#pragma unroll
            for (int j = 0; j < JT; ++j) {
                float t = x + ce_s[j][h];
                // exact GELU: t * Phi(t)
                float g = t * normcdff(t);
                acc[j] = fmaf(w, g, acc[j]);
            }
        }
        // butterfly reduce (all lanes end with full sums)
#pragma unroll
        for (int off = 16; off; off >>= 1)
#pragma unroll
            for (int j = 0; j < JT; ++j)
                acc[j] += __shfl_xor_sync(0xffffffffu, acc[j], off);

#pragma unroll
        for (int j = 0; j < JT; ++j) {
            float logit = acc[j] + bias2;
            partial[j] += 1.0f / (1.0f + expf(-logit));
        }
    }

    if (lane == 0) {
#pragma unroll
        for (int j = 0; j < JT; ++j) red[warp][j] = partial[j];
    }
    __syncthreads();
    if (tid < JT) {
        float s = 0.0f;
#pragma unroll
        for (int w = 0; w < 8; ++w) s += red[w][tid];
        out[i * VC + jt * JT + tid] = s * (1.0f / BC);
    }
}

// ---------------------------------------------------------------------------
extern "C" void kernel_launch(void* const* d_in, const int* in_sizes, int n_in,
                              void* d_out, int out_size) {
    const float* state  = (const float*)d_in[0];
    const float* action = (const float*)d_in[1];
    const float* embed  = (const float*)d_in[2];
    const float* W1     = (const float*)d_in[3];
    const float* b1     = (const float*)d_in[4];
    const float* W2     = (const float*)d_in[5];
    const float* b2     = (const float*)d_in[6];
    float* out          = (float*)d_out;

    gemm_pre_kernel<<<24, 256>>>(state, action, embed, W1);
    score_kernel<<<VC * (VC / JT), 256>>>(b1, W2, b2, out);
}

// round 2
// speedup vs baseline: 2.3802x; 2.3802x over previous
#include <cuda_runtime.h>
#include <math.h>

#define DIMC 512
#define HC   1024
#define BC   64
#define VC   64
#define JT   8   // j-tile per block

// scratch: [0:64*1024) cause_h, [64*1024:128*1024) effect_h, [128*1024:192*1024) ctx_h
__device__ float g_pre[3 * BC * HC];

__device__ __forceinline__ float ex2_approx(float x) {
    float y; asm("ex2.approx.f32 %0, %1;" : "=f"(y) : "f"(x)); return y;
}
__device__ __forceinline__ float rcp_approx(float x) {
    float y; asm("rcp.approx.f32 %0, %1;" : "=f"(y) : "f"(x)); return y;
}

// Exact-form GELU via Abramowitz-Stegun 7.1.25 erf (abs err <= 2.5e-5).
// gelu(x) = 0.5*x*(1 + erf(x/sqrt(2)))
__device__ __forceinline__ float gelu_fast(float x) {
    const float c_isqrt2 = 0.70710678118f;
    const float c_l2e_h  = 0.72134752044f;   // 0.5/ln(2)
    const float p  = 0.47047f;
    const float a1 = 0.3480242f;
    const float a2 = -0.0958798f;
    const float a3 = 0.7478556f;

    float z   = fabsf(x) * c_isqrt2;
    float den = fmaf(p, z, 1.0f);
    float t   = rcp_approx(den);
    float s   = x * x;
    float e   = ex2_approx(-c_l2e_h * s);    // exp(-x^2/2)
    float P   = fmaf(fmaf(a3, t, a2), t, a1);
    float Pt  = P * t;
    float r   = fmaf(-Pt, e, 1.0f);          // erf(|z|)
    float rs  = copysignf(r, x);             // erf(z) signed
    float hx  = 0.5f * x;
    return fmaf(hx, rs, hx);                 // 0.5x(1+erf)
}

// ---------------------------------------------------------------------------
// Kernel 1: pre-activations. grid = 3*8 blocks (m, 128-col tile), 256 threads.
// ---------------------------------------------------------------------------
__global__ void gemm_pre_kernel(const float* __restrict__ state,
                                const float* __restrict__ action,
                                const float* __restrict__ embed,
                                const float* __restrict__ W1) {
    const int m  = blockIdx.x >> 3;
    const int hb = blockIdx.x & 7;
    const int tid = threadIdx.x;

    __shared__ float As[64][17];
    __shared__ float Ws[16][128];

    const int rgrp = tid >> 5;
    const int cgrp = tid & 31;

    float acc[8][4];
#pragma unroll
    for (int i = 0; i < 8; ++i)
#pragma unroll
        for (int j = 0; j < 4; ++j) acc[i][j] = 0.0f;

    const float* Wbase = W1 + (size_t)(m * DIMC) * HC + hb * 128;

    for (int k0 = 0; k0 < DIMC; k0 += 16) {
        for (int t = tid; t < 64 * 16; t += 256) {
            int r = t >> 4, k = t & 15;
            float a;
            if (m == 2) a = state[r * DIMC + k0 + k] + action[r * DIMC + k0 + k];
            else        a = embed[r * DIMC + k0 + k];
            As[r][k] = a;
        }
        for (int t = tid; t < 16 * 128; t += 256) {
            int k = t >> 7, c = t & 127;
            Ws[k][c] = Wbase[(size_t)(k0 + k) * HC + c];
        }
        __syncthreads();
#pragma unroll
        for (int k = 0; k < 16; ++k) {
            float4 w4 = *reinterpret_cast<const float4*>(&Ws[k][cgrp * 4]);
#pragma unroll
            for (int i = 0; i < 8; ++i) {
                float a = As[rgrp * 8 + i][k];
                acc[i][0] = fmaf(a, w4.x, acc[i][0]);
                acc[i][1] = fmaf(a, w4.y, acc[i][1]);
                acc[i][2] = fmaf(a, w4.z, acc[i][2]);
                acc[i][3] = fmaf(a, w4.w, acc[i][3]);
            }
        }
        __syncthreads();
    }

    float* out = g_pre + (size_t)(m * BC) * HC;
#pragma unroll
    for (int i = 0; i < 8; ++i) {
        int r = rgrp * 8 + i;
        float4 v = make_float4(acc[i][0], acc[i][1], acc[i][2], acc[i][3]);
        *reinterpret_cast<float4*>(&out[(size_t)r * HC + hb * 128 + cgrp * 4]) = v;
    }
}

// ---------------------------------------------------------------------------
// Kernel 2: scores[i][j] = mean_b sigmoid(b2 + sum_h w2[h]*gelu(ctx[b,h]+ce[i,j,h]))
// grid = 512 blocks (i, j-tile of 8); 256 threads = 8 warps, warp-per-b (x8).
// float4 inner loop; each ctx value loaded once, reused across JT j's.
// ---------------------------------------------------------------------------
__global__ void score_kernel(const float* __restrict__ b1,
                             const float* __restrict__ W2,
                             const float* __restrict__ b2,
                             float* __restrict__ out) {
    const int i  = blockIdx.x >> 3;
    const int jt = blockIdx.x & 7;

    __shared__ float ce_s[JT][HC];
    __shared__ float w2s[HC];
    __shared__ float red[8][JT];

    const int tid  = threadIdx.x;
    const int warp = tid >> 5;
    const int lane = tid & 31;

    const float* cause  = g_pre;
    const float* effect = g_pre + BC * HC;
    const float* ctx    = g_pre + 2 * BC * HC;

    for (int t = tid; t < JT * HC; t += 256) {
        int j = t >> 10, h = t & (HC - 1);
        ce_s[j][h] = cause[i * HC + h] + effect[(jt * JT + j) * HC + h] + b1[h];
    }
    for (int t = tid; t < HC; t += 256) w2s[t] = W2[t];
    __syncthreads();

    const float bias2 = b2[0];
    float partial[JT];
#pragma unroll
    for (int j = 0; j < JT; ++j) partial[j] = 0.0f;

    for (int bi = 0; bi < 8; ++bi) {
        const int b = bi * 8 + warp;
        const float4* ctxb4 = reinterpret_cast<const float4*>(ctx + (size_t)b * HC);

        float acc[JT];
#pragma unroll
        for (int j = 0; j < JT; ++j) acc[j] = 0.0f;

        // HC/4 = 256 float4's, 32 lanes -> 8 iterations
        for (int v = lane; v < HC / 4; v += 32) {
            const float4 x4 = ctxb4[v];
            const float4 w4 = reinterpret_cast<const float4*>(w2s)[v];
#pragma unroll
            for (int j = 0; j < JT; ++j) {
                const float4 c4 = reinterpret_cast<const float4*>(ce_s[j])[v];
                float g0 = gelu_fast(x4.x + c4.x);
                float g1 = gelu_fast(x4.y + c4.y);
                float g2 = gelu_fast(x4.z + c4.z);
                float g3 = gelu_fast(x4.w + c4.w);
                acc[j] = fmaf(w4.x, g0, acc[j]);
                acc[j] = fmaf(w4.y, g1, acc[j]);
                acc[j] = fmaf(w4.z, g2, acc[j]);
                acc[j] = fmaf(w4.w, g3, acc[j]);
            }
        }
#pragma unroll
        for (int off = 16; off; off >>= 1)
#pragma unroll
            for (int j = 0; j < JT; ++j)
                acc[j] += __shfl_xor_sync(0xffffffffu, acc[j], off);

#pragma unroll
        for (int j = 0; j < JT; ++j) {
            float logit = acc[j] + bias2;
            // sigmoid(x) = 1/(1+exp(-x)) via ex2/rcp
            float en = ex2_approx(-1.44269504f * logit);
            partial[j] += rcp_approx(1.0f + en);
        }
    }

    if (lane == 0) {
#pragma unroll
        for (int j = 0; j < JT; ++j) red[warp][j] = partial[j];
    }
    __syncthreads();
    if (tid < JT) {
        float s = 0.0f;
#pragma unroll
        for (int w = 0; w < 8; ++w) s += red[w][tid];
        out[i * VC + jt * JT + tid] = s * (1.0f / BC);
    }
}

// ---------------------------------------------------------------------------
extern "C" void kernel_launch(void* const* d_in, const int* in_sizes, int n_in,
                              void* d_out, int out_size) {
    const float* state  = (const float*)d_in[0];
    const float* action = (const float*)d_in[1];
    const float* embed  = (const float*)d_in[2];
    const float* W1     = (const float*)d_in[3];
    const float* b1     = (const float*)d_in[4];
    const float* W2     = (const float*)d_in[5];
    const float* b2     = (const float*)d_in[6];
    float* out          = (float*)d_out;

    gemm_pre_kernel<<<24, 256>>>(state, action, embed, W1);
    score_kernel<<<VC * (VC / JT), 256>>>(b1, W2, b2, out);
}

// round 3
// speedup vs baseline: 3.5328x; 1.4842x over previous
#include <cuda_runtime.h>
#include <math.h>

#define DIMC 512
#define HC   1024
#define BC   64
#define VC   64
#define JT   8

__device__ __align__(16) float g_pre[3 * BC * HC];

__device__ __forceinline__ float ex2_approx(float x) {
    float y; asm("ex2.approx.f32 %0, %1;" : "=f"(y) : "f"(x)); return y;
}
__device__ __forceinline__ float rcp_approx(float x) {
    float y; asm("rcp.approx.f32 %0, %1;" : "=f"(y) : "f"(x)); return y;
}
__device__ __forceinline__ unsigned long long pk2(float lo, float hi) {
    unsigned long long r; asm("mov.b64 %0, {%1,%2};" : "=l"(r) : "f"(lo), "f"(hi)); return r;
}
__device__ __forceinline__ void upk2(unsigned long long v, float& lo, float& hi) {
    asm("mov.b64 {%0,%1}, %2;" : "=f"(lo), "=f"(hi) : "l"(v));
}
__device__ __forceinline__ unsigned long long add2(unsigned long long a, unsigned long long b) {
    unsigned long long r; asm("add.rn.f32x2 %0, %1, %2;" : "=l"(r) : "l"(a), "l"(b)); return r;
}
__device__ __forceinline__ unsigned long long mul2(unsigned long long a, unsigned long long b) {
    unsigned long long r; asm("mul.rn.f32x2 %0, %1, %2;" : "=l"(r) : "l"(a), "l"(b)); return r;
}
__device__ __forceinline__ unsigned long long fma2(unsigned long long a, unsigned long long b, unsigned long long c) {
    unsigned long long r; asm("fma.rn.f32x2 %0, %1, %2, %3;" : "=l"(r) : "l"(a), "l"(b), "l"(c)); return r;
}

// tanh-form GELU sigmoid-arg constants, pre-multiplied by -log2(e):
// a(t) = t*(-2.3022079 - 0.1029428*t^2);  sigma = 1/(1+2^a);  gelu = t*sigma
#define K1F (-2.3022079f)
#define K3F (-0.1029428f)

// ---------------------------------------------------------------------------
// Kernel 1: pre-activations. grid = 3*32 = 96 blocks (m, 32-col tile).
// ---------------------------------------------------------------------------
__global__ __launch_bounds__(256) void gemm_pre_kernel(
        const float* __restrict__ state, const float* __restrict__ action,
        const float* __restrict__ embed, const float* __restrict__ W1) {
    const int m  = blockIdx.x >> 5;   // 0..2
    const int ct = blockIdx.x & 31;   // col tile: cols ct*32 .. +32
    const int tid = threadIdx.x;

    __shared__ float As[64][33];
    __shared__ float Ws[32][36];      // 36 floats/row -> 16B-aligned rows

    const int cg = tid >> 5;          // 0..7 -> cols cg*4..+4 (warp-uniform)
    const int rg = tid & 31;          // rows rg*2, rg*2+1

    float acc[8];
#pragma unroll
    for (int i = 0; i < 8; ++i) acc[i] = 0.0f;

    const float* Wbase = W1 + (size_t)(m * DIMC) * HC + ct * 32;

    for (int k0 = 0; k0 < DIMC; k0 += 32) {
        for (int t = tid; t < 64 * 32; t += 256) {
            int r = t >> 5, k = t & 31;
            float a;
            if (m == 2) a = state[r * DIMC + k0 + k] + action[r * DIMC + k0 + k];
            else        a = embed[r * DIMC + k0 + k];
            As[r][k] = a;
        }
        for (int t = tid; t < 32 * 32; t += 256) {
            int k = t >> 5, c = t & 31;
            Ws[k][c] = Wbase[(size_t)(k0 + k) * HC + c];
        }
        __syncthreads();
#pragma unroll
        for (int k = 0; k < 32; ++k) {
            float4 w4 = *reinterpret_cast<const float4*>(&Ws[k][cg * 4]);
            float a0 = As[rg * 2][k];
            float a1 = As[rg * 2 + 1][k];
            acc[0] = fmaf(a0, w4.x, acc[0]);
            acc[1] = fmaf(a0, w4.y, acc[1]);
            acc[2] = fmaf(a0, w4.z, acc[2]);
            acc[3] = fmaf(a0, w4.w, acc[3]);
            acc[4] = fmaf(a1, w4.x, acc[4]);
            acc[5] = fmaf(a1, w4.y, acc[5]);
            acc[6] = fmaf(a1, w4.z, acc[6]);
            acc[7] = fmaf(a1, w4.w, acc[7]);
        }
        __syncthreads();
    }

    float* out = g_pre + (size_t)(m * BC) * HC + ct * 32 + cg * 4;
#pragma unroll
    for (int r = 0; r < 2; ++r) {
        float4 v = make_float4(acc[r*4+0], acc[r*4+1], acc[r*4+2], acc[r*4+3]);
        *reinterpret_cast<float4*>(&out[(size_t)(rg * 2 + r) * HC]) = v;
    }
}

// ---------------------------------------------------------------------------
// Kernel 2: scores. grid=512 (i, j-tile of 8), 256 thr = 8 warps, warp-per-b.
// Packed f32x2 math; 1 rcp shared per h-pair (1.5 MUFU/eval).
// ---------------------------------------------------------------------------
__global__ __launch_bounds__(256) void score_kernel(
        const float* __restrict__ b1, const float* __restrict__ W2,
        const float* __restrict__ b2, float* __restrict__ out) {
    const int i  = blockIdx.x >> 3;
    const int jt = blockIdx.x & 7;

    __shared__ __align__(16) float ce_s[JT][HC];
    __shared__ __align__(16) float w2s[HC];
    __shared__ float red[8][JT];

    const int tid  = threadIdx.x;
    const int warp = tid >> 5;
    const int lane = tid & 31;

    const float* cause  = g_pre;
    const float* effect = g_pre + BC * HC;
    const float* ctx    = g_pre + 2 * BC * HC;

    // stage ce = cause + effect + b1 (vectorized)
    {
        const float4* c4 = reinterpret_cast<const float4*>(cause + i * HC);
        const float4* b4 = reinterpret_cast<const float4*>(b1);
        for (int t = tid; t < JT * HC / 4; t += 256) {
            int j = t >> 8, v = t & 255;
            float4 e4 = reinterpret_cast<const float4*>(effect + (jt * JT + j) * HC)[v];
            float4 cc = c4[v], bb = b4[v];
            float4 r;
            r.x = cc.x + e4.x + bb.x;
            r.y = cc.y + e4.y + bb.y;
            r.z = cc.z + e4.z + bb.z;
            r.w = cc.w + e4.w + bb.w;
            reinterpret_cast<float4*>(ce_s[j])[v] = r;
        }
        for (int t = tid; t < HC / 4; t += 256)
            reinterpret_cast<float4*>(w2s)[t] = reinterpret_cast<const float4*>(W2)[t];
    }
    __syncthreads();

    const unsigned long long K1p = pk2(K1F, K1F);
    const unsigned long long K3p = pk2(K3F, K3F);
    const float bias2 = b2[0];

    float partial[JT];
#pragma unroll
    for (int j = 0; j < JT; ++j) partial[j] = 0.0f;

    for (int bi = 0; bi < 8; ++bi) {
        const int b = bi * 8 + warp;
        const ulonglong2* ctx2 = reinterpret_cast<const ulonglong2*>(ctx + (size_t)b * HC);
        const ulonglong2* w22  = reinterpret_cast<const ulonglong2*>(w2s);

        unsigned long long acc2[JT];
#pragma unroll
        for (int j = 0; j < JT; ++j) acc2[j] = 0ull;

        for (int v = lane; v < HC / 4; v += 32) {
            const ulonglong2 x2 = ctx2[v];
            const ulonglong2 w2 = w22[v];
#pragma unroll
            for (int j = 0; j < JT; ++j) {
                const ulonglong2 c2 = reinterpret_cast<const ulonglong2*>(ce_s[j])[v];
#pragma unroll
                for (int p = 0; p < 2; ++p) {
                    unsigned long long xp = p ? x2.y : x2.x;
                    unsigned long long cp = p ? c2.y : c2.x;
                    unsigned long long wp = p ? w2.y : w2.x;
                    unsigned long long t2 = add2(xp, cp);
                    unsigned long long s2 = mul2(t2, t2);
                    unsigned long long p2 = fma2(s2, K3p, K1p);
                    unsigned long long a2 = mul2(p2, t2);
                    float al, ah; upk2(a2, al, ah);
                    al = fminf(al, 80.0f);
                    ah = fminf(ah, 80.0f);
                    float el = ex2_approx(al);
                    float eh = ex2_approx(ah);
                    float dl = el + 1.0f;
                    float dh = eh + 1.0f;
                    float R  = rcp_approx(dl * dh);
                    float tl, th; upk2(t2, tl, th);
                    float gl = (tl * dh) * R;   // t * sigma
                    float gh = (th * dl) * R;
                    acc2[j] = fma2(wp, pk2(gl, gh), acc2[j]);
                }
            }
        }

        float acc[JT];
#pragma unroll
        for (int j = 0; j < JT; ++j) {
            float lo, hi; upk2(acc2[j], lo, hi);
            acc[j] = lo + hi;
        }
#pragma unroll
        for (int off = 16; off; off >>= 1)
#pragma unroll
            for (int j = 0; j < JT; ++j)
                acc[j] += __shfl_xor_sync(0xffffffffu, acc[j], off);

#pragma unroll
        for (int j = 0; j < JT; ++j) {
            float logit = acc[j] + bias2;
            float en = ex2_approx(-1.44269504f * logit);
            partial[j] += rcp_approx(1.0f + en);
        }
    }

    if (lane == 0) {
#pragma unroll
        for (int j = 0; j < JT; ++j) red[warp][j] = partial[j];
    }
    __syncthreads();
    if (tid < JT) {
        float s = 0.0f;
#pragma unroll
        for (int w = 0; w < 8; ++w) s += red[w][tid];
        out[i * VC + jt * JT + tid] = s * (1.0f / BC);
    }
}

// ---------------------------------------------------------------------------
extern "C" void kernel_launch(void* const* d_in, const int* in_sizes, int n_in,
                              void* d_out, int out_size) {
    const float* state  = (const float*)d_in[0];
    const float* action = (const float*)d_in[1];
    const float* embed  = (const float*)d_in[2];
    const float* W1     = (const float*)d_in[3];
    const float* b1     = (const float*)d_in[4];
    const float* W2     = (const float*)d_in[5];
    const float* b2     = (const float*)d_in[6];
    float* out          = (float*)d_out;

    gemm_pre_kernel<<<96, 256>>>(state, action, embed, W1);
    score_kernel<<<VC * (VC / JT), 256>>>(b1, W2, b2, out);
}